// round 5
// baseline (speedup 1.0000x reference)
#include <cuda_runtime.h>
#include <cuda_fp16.h>

#define NF    22528          // NUM_FEATURES
#define NOUT  520            // HIDDEN + BUCKET_NB
#define HID   512
#define NROWS 8192
#define NB    8
#define MAXIDX 512
#define SCALE_O 400.0f

// Scratch: fp16 transposed FT weights (23.4 MB) + fp16 W1 (512 KB) + row order
__device__ __half g_WftTh[(size_t)NF * NOUT];
__device__ __half g_W1h[NB * 32 * 1024];
__device__ int    g_rows[NB * NROWS];
__device__ int    g_order[NROWS];
__device__ int    g_cnt[NB];

// ---------------------------------------------------------------------------
// Kernel: zero counters, then bin rows by bucket (single launch, grid sync via
// separate kernels is avoided by zeroing in a tiny prologue kernel)
// ---------------------------------------------------------------------------
__global__ void zero_cnt() {
    if (threadIdx.x < NB) g_cnt[threadIdx.x] = 0;
}

__global__ void bin_rows(const int* __restrict__ buckets) {
    int r = blockIdx.x * 256 + threadIdx.x;
    if (r < NROWS) {
        int k = buckets[r];
        int p = atomicAdd(&g_cnt[k], 1);
        g_rows[k * NROWS + p] = r;
    }
}

__global__ void pack_rows() {
    __shared__ int off[NB];
    if (threadIdx.x == 0) {
        int s = 0;
        for (int k = 0; k < NB; k++) { off[k] = s; s += g_cnt[k]; }
    }
    __syncthreads();
    for (int k = 0; k < NB; k++) {
        int c = g_cnt[k], o = off[k];
        for (int i = threadIdx.x; i < c; i += 256)
            g_order[o + i] = g_rows[k * NROWS + i];
    }
}

// ---------------------------------------------------------------------------
// Kernel: transpose W_ft [520, 22528] -> g_WftTh [22528, 520] (fp16)
// ---------------------------------------------------------------------------
__global__ void transpose_wft(const float* __restrict__ W) {
    __shared__ float tile[32][33];
    int f0 = blockIdx.x * 32;
    int o0 = blockIdx.y * 32;
    int tx = threadIdx.x;   // 0..31
    int ty = threadIdx.y;   // 0..7
#pragma unroll
    for (int i = 0; i < 4; i++) {
        int o = o0 + ty + 8 * i;
        float v = 0.0f;
        if (o < NOUT) v = W[(size_t)o * NF + f0 + tx];
        tile[ty + 8 * i][tx] = v;
    }
    __syncthreads();
#pragma unroll
    for (int i = 0; i < 4; i++) {
        int f = f0 + ty + 8 * i;
        int o = o0 + tx;
        if (o < NOUT)
            g_WftTh[(size_t)f * NOUT + o] = __float2half_rn(tile[tx][ty + 8 * i]);
    }
}

// ---------------------------------------------------------------------------
// Kernel: convert W1 to fp16
// ---------------------------------------------------------------------------
__global__ void conv_w1(const float* __restrict__ W1) {
    int i = blockIdx.x * 256 + threadIdx.x;
    g_W1h[i] = __float2half_rn(W1[i]);
}

// ---------------------------------------------------------------------------
// Main kernel
// ---------------------------------------------------------------------------
__device__ __forceinline__ float clip01(float v) {
    return fminf(fmaxf(v, 0.0f), 1.0f);
}

__device__ __forceinline__ void push4(const float4& v, int base,
                                      int* __restrict__ idx, int* __restrict__ cnt) {
    if (v.x != 0.0f) { int p = atomicAdd(cnt, 1); if (p < MAXIDX) idx[p] = base + 0; }
    if (v.y != 0.0f) { int p = atomicAdd(cnt, 1); if (p < MAXIDX) idx[p] = base + 1; }
    if (v.z != 0.0f) { int p = atomicAdd(cnt, 1); if (p < MAXIDX) idx[p] = base + 2; }
    if (v.w != 0.0f) { int p = atomicAdd(cnt, 1); if (p < MAXIDX) idx[p] = base + 3; }
}

__global__ __launch_bounds__(256, 4) void nnue_row(
    const float* __restrict__ wf,      // [8192, 22528]
    const float* __restrict__ bfeat,   // [8192, 22528]
    const float* __restrict__ stm_arr, // [8192, 1]
    const int*   __restrict__ buckets, // [8192]
    const float* __restrict__ b_ft,    // [520]
    const float* __restrict__ b1,      // [8, 32]
    const float* __restrict__ W2,      // [8, 32, 32]
    const float* __restrict__ b2,      // [8, 32]
    const float* __restrict__ W3,      // [8, 1, 32]
    const float* __restrict__ b3,      // [8, 1]
    float*       __restrict__ out)     // [8192]
{
    __shared__ int   s_idxW[MAXIDX];
    __shared__ int   s_idxB[MAXIDX];
    __shared__ int   s_cntW, s_cntB;
    __shared__ float s_x[1024];
    __shared__ float s_h1[32];

    const int row = g_order[blockIdx.x];    // bucket-grouped ordering
    const int tid = threadIdx.x;

    if (tid == 0) { s_cntW = 0; s_cntB = 0; }
    __syncthreads();

    // ---- Phase A: high-MLP stream scan (batches of 8 front-loaded LDG.128) ----
    {
        const float4* w4 = (const float4*)(wf    + (size_t)row * NF);
        const float4* b4 = (const float4*)(bfeat + (size_t)row * NF);
        int u = tid;                         // NF/4 = 5632 = 22 * 256
#pragma unroll
        for (int batch = 0; batch < 5; batch++) {     // 5 * 4 = 20 iters
            float4 vw[4], vb[4];
#pragma unroll
            for (int j = 0; j < 4; j++) {
                vw[j] = __ldcs(&w4[u + j * 256]);
                vb[j] = __ldcs(&b4[u + j * 256]);
            }
#pragma unroll
            for (int j = 0; j < 4; j++) {
                push4(vw[j], 4 * (u + j * 256), s_idxW, &s_cntW);
                push4(vb[j], 4 * (u + j * 256), s_idxB, &s_cntB);
            }
            u += 1024;
        }
        {   // tail: 2 iterations
            float4 vw0 = __ldcs(&w4[u]);
            float4 vb0 = __ldcs(&b4[u]);
            float4 vw1 = __ldcs(&w4[u + 256]);
            float4 vb1 = __ldcs(&b4[u + 256]);
            push4(vw0, 4 * u,          s_idxW, &s_cntW);
            push4(vb0, 4 * u,          s_idxB, &s_cntB);
            push4(vw1, 4 * (u + 256),  s_idxW, &s_cntW);
            push4(vb1, 4 * (u + 256),  s_idxB, &s_cntB);
        }
    }
    __syncthreads();
    const int cw = min(s_cntW, MAXIDX);
    const int cb = min(s_cntB, MAXIDX);
    const int k  = buckets[row];

    // ---- Phase B: register accumulators; fp16 gather (thread t: cols 2t,2t+1)
    float2 aw = *(const float2*)(b_ft + 2 * tid);
    float2 ab = aw;
    float psw = 0.0f, psb = 0.0f;    // b_ft cancels in the psqt difference

#pragma unroll 4
    for (int i = 0; i < cw; i++) {
        const __half* r = g_WftTh + (size_t)s_idxW[i] * NOUT;
        float2 v = __half22float2(*(const __half2*)(r + 2 * tid));
        aw.x += v.x; aw.y += v.y;
        if (tid == 0) psw += __half2float(r[512 + k]);
    }
#pragma unroll 4
    for (int i = 0; i < cb; i++) {
        const __half* r = g_WftTh + (size_t)s_idxB[i] * NOUT;
        float2 v = __half22float2(*(const __half2*)(r + 2 * tid));
        ab.x += v.x; ab.y += v.y;
        if (tid == 0) psb += __half2float(r[512 + k]);
    }

    // ---- Phase C: stm-ordered clip into x[1024] ----
    const float stm = stm_arr[row];   // exactly 0.0 or 1.0
    const bool wfirst = (stm == 0.0f);
    float2 xf = wfirst ? aw : ab;
    float2 xs = wfirst ? ab : aw;

    float2* x2 = (float2*)s_x;
    x2[tid]       = make_float2(clip01(xf.x), clip01(xf.y));
    x2[256 + tid] = make_float2(clip01(xs.x), clip01(xs.y));
    __syncthreads();

    // ---- Layer 1 (fp16 W1, L1-resident via bucket grouping) ----
    const int warp = tid >> 5, lane = tid & 31;
    const __half2* W1k = (const __half2*)(g_W1h + (size_t)k * 32 * 1024);
    const float2*  sx2 = (const float2*)s_x;
#pragma unroll
    for (int oo = 0; oo < 4; oo++) {
        const int o = warp * 4 + oo;
        const __half2* wr = W1k + o * 512;
        float s = 0.0f;
#pragma unroll
        for (int m = 0; m < 16; m++) {
            float2 xv = sx2[lane + 32 * m];                  // conflict-free
            float2 wv = __half22float2(__ldg(&wr[lane + 32 * m]));
            s += xv.x * wv.x + xv.y * wv.y;
        }
#pragma unroll
        for (int d = 16; d; d >>= 1) s += __shfl_xor_sync(0xFFFFFFFFu, s, d);
        if (lane == 0) s_h1[o] = clip01(s + __ldg(&b1[k * 32 + o]));
    }
    __syncthreads();

    // ---- Layers 2+3 + psqt + output: warp 0 ----
    if (warp == 0) {
        const float* W2k = W2 + k * 32 * 32;
        float s = 0.0f;
#pragma unroll
        for (int i = 0; i < 32; i++)
            s += s_h1[i] * __ldg(&W2k[lane * 32 + i]);
        float h2 = clip01(s + __ldg(&b2[k * 32 + lane]));

        float p = h2 * __ldg(&W3[k * 32 + lane]);
#pragma unroll
        for (int d = 16; d; d >>= 1) p += __shfl_xor_sync(0xFFFFFFFFu, p, d);

        if (lane == 0) {
            float psqt = (psw - psb) * (0.5f - stm);
            out[row] = (p + __ldg(&b3[k]) + psqt) * SCALE_O;
        }
    }
}

// ---------------------------------------------------------------------------
// Harness entry
// ---------------------------------------------------------------------------
extern "C" void kernel_launch(void* const* d_in, const int* in_sizes, int n_in,
                              void* d_out, int out_size) {
    const float* wf    = (const float*)d_in[0];
    const float* bfeat = (const float*)d_in[1];
    const float* stm   = (const float*)d_in[2];
    const int*   bkt   = (const int*)  d_in[3];
    const float* W_ft  = (const float*)d_in[4];
    const float* b_ft  = (const float*)d_in[5];
    const float* W1    = (const float*)d_in[6];
    const float* b1    = (const float*)d_in[7];
    const float* W2    = (const float*)d_in[8];
    const float* b2    = (const float*)d_in[9];
    const float* W3    = (const float*)d_in[10];
    const float* b3    = (const float*)d_in[11];
    float* out = (float*)d_out;

    zero_cnt<<<1, 32>>>();
    bin_rows<<<NROWS / 256, 256>>>(bkt);
    pack_rows<<<1, 256>>>();
    dim3 tg(NF / 32, (NOUT + 31) / 32);
    transpose_wft<<<tg, dim3(32, 8)>>>(W_ft);
    conv_w1<<<1024, 256>>>(W1);
    nnue_row<<<NROWS, 256>>>(wf, bfeat, stm, bkt, b_ft,
                             b1, W2, b2, W3, b3, out);
}

// round 7
// speedup vs baseline: 1.1695x; 1.1695x over previous
#include <cuda_runtime.h>

#define NF    22528          // NUM_FEATURES
#define NOUT  520            // HIDDEN + BUCKET_NB
#define HID   512
#define NROWS 8192
#define NB    8
#define MAXIDX 512
#define SCALE_O 400.0f

// Transposed feature-transform weights: W_ftT[f][o] = W_ft[o][f]. 46.9 MB.
__device__ float g_WftT[(size_t)NF * NOUT];

// ---------------------------------------------------------------------------
// Kernel 0: transpose W_ft [520, 22528] -> g_WftT [22528, 520]
// ---------------------------------------------------------------------------
__global__ void transpose_wft(const float* __restrict__ W) {
    __shared__ float tile[32][33];
    int f0 = blockIdx.x * 32;
    int o0 = blockIdx.y * 32;
    int tx = threadIdx.x;   // 0..31
    int ty = threadIdx.y;   // 0..7
#pragma unroll
    for (int i = 0; i < 4; i++) {
        int o = o0 + ty + 8 * i;
        float v = 0.0f;
        if (o < NOUT) v = W[(size_t)o * NF + f0 + tx];
        tile[ty + 8 * i][tx] = v;
    }
    __syncthreads();
#pragma unroll
    for (int i = 0; i < 4; i++) {
        int f = f0 + ty + 8 * i;
        int o = o0 + tx;
        if (o < NOUT)
            g_WftT[(size_t)f * NOUT + o] = tile[tx][ty + 8 * i];
    }
}

// ---------------------------------------------------------------------------
// Main kernel: one block per batch row
// ---------------------------------------------------------------------------
__device__ __forceinline__ float clip01(float v) {
    return fminf(fmaxf(v, 0.0f), 1.0f);
}

__global__ __launch_bounds__(256, 6) void nnue_row(
    const float* __restrict__ wf,      // [8192, 22528]
    const float* __restrict__ bfeat,   // [8192, 22528]
    const float* __restrict__ stm_arr, // [8192, 1]
    const int*   __restrict__ buckets, // [8192]
    const float* __restrict__ b_ft,    // [520]
    const float* __restrict__ W1,      // [8, 32, 1024]
    const float* __restrict__ b1,      // [8, 32]
    const float* __restrict__ W2,      // [8, 32, 32]
    const float* __restrict__ b2,      // [8, 32]
    const float* __restrict__ W3,      // [8, 1, 32]
    const float* __restrict__ b3,      // [8, 1]
    float*       __restrict__ out)     // [8192]
{
    __shared__ int   s_idxW[MAXIDX];
    __shared__ int   s_idxB[MAXIDX];
    __shared__ int   s_cntW, s_cntB;
    __shared__ float s_x[1024];
    __shared__ float s_h1[32];

    const int row = blockIdx.x;
    const int tid = threadIdx.x;

    if (tid == 0) { s_cntW = 0; s_cntB = 0; }
    __syncthreads();

    // ---- Phase A: lean integer-test stream scan ----
    // Features are exactly 0.0f or 1.0f -> nonzero iff bit pattern != 0.
    {
        const uint4* w4 = (const uint4*)(wf    + (size_t)row * NF);
        const uint4* b4 = (const uint4*)(bfeat + (size_t)row * NF);
#pragma unroll 2
        for (int u = tid; u < NF / 4; u += 256) {
            uint4 v = __ldcs(&w4[u]);
            uint4 q = __ldcs(&b4[u]);
            if (v.x | v.y | v.z | v.w) {       // rare (~0.6% of thread-iters)
                if (v.x) { int p = atomicAdd(&s_cntW, 1); if (p < MAXIDX) s_idxW[p] = 4 * u + 0; }
                if (v.y) { int p = atomicAdd(&s_cntW, 1); if (p < MAXIDX) s_idxW[p] = 4 * u + 1; }
                if (v.z) { int p = atomicAdd(&s_cntW, 1); if (p < MAXIDX) s_idxW[p] = 4 * u + 2; }
                if (v.w) { int p = atomicAdd(&s_cntW, 1); if (p < MAXIDX) s_idxW[p] = 4 * u + 3; }
            }
            if (q.x | q.y | q.z | q.w) {
                if (q.x) { int p = atomicAdd(&s_cntB, 1); if (p < MAXIDX) s_idxB[p] = 4 * u + 0; }
                if (q.y) { int p = atomicAdd(&s_cntB, 1); if (p < MAXIDX) s_idxB[p] = 4 * u + 1; }
                if (q.z) { int p = atomicAdd(&s_cntB, 1); if (p < MAXIDX) s_idxB[p] = 4 * u + 2; }
                if (q.w) { int p = atomicAdd(&s_cntB, 1); if (p < MAXIDX) s_idxB[p] = 4 * u + 3; }
            }
        }
    }
    __syncthreads();
    const int cw = min(s_cntW, MAXIDX);
    const int cb = min(s_cntB, MAXIDX);
    const int k  = buckets[row];

    // ---- Phase B: register accumulators; float2 gather (thread t: cols 2t,2t+1)
    float2 aw = *(const float2*)(b_ft + 2 * tid);
    float2 ab = aw;
    float psw = 0.0f, psb = 0.0f;   // b_ft cancels in the psqt difference

#pragma unroll 4
    for (int i = 0; i < cw; i++) {
        const float* r = g_WftT + (size_t)s_idxW[i] * NOUT;
        float2 v = *(const float2*)(r + 2 * tid);
        aw.x += v.x; aw.y += v.y;
        if (tid == 0) psw += r[512 + k];
    }
#pragma unroll 4
    for (int i = 0; i < cb; i++) {
        const float* r = g_WftT + (size_t)s_idxB[i] * NOUT;
        float2 v = *(const float2*)(r + 2 * tid);
        ab.x += v.x; ab.y += v.y;
        if (tid == 0) psb += r[512 + k];
    }

    // ---- Phase C: stm-ordered clip into x[1024] ----
    const float stm = stm_arr[row];   // exactly 0.0 or 1.0
    const bool wfirst = (stm == 0.0f);
    float2 xf = wfirst ? aw : ab;
    float2 xs = wfirst ? ab : aw;

    float2* x2 = (float2*)s_x;
    x2[tid]       = make_float2(clip01(xf.x), clip01(xf.y));
    x2[256 + tid] = make_float2(clip01(xs.x), clip01(xs.y));
    __syncthreads();

    // ---- Layer 1: warp w computes outputs 4w..4w+3 (float2 dot from smem/L2)
    const int warp = tid >> 5, lane = tid & 31;
    const float2* W1k = (const float2*)(W1 + (size_t)k * 32 * 1024);
    const float2* sx2 = (const float2*)s_x;
#pragma unroll
    for (int oo = 0; oo < 4; oo++) {
        const int o = warp * 4 + oo;
        const float2* wr = W1k + o * 512;
        float s = 0.0f;
#pragma unroll
        for (int m = 0; m < 16; m++) {
            float2 xv = sx2[lane + 32 * m];          // conflict-free
            float2 wv = __ldg(&wr[lane + 32 * m]);
            s += xv.x * wv.x + xv.y * wv.y;
        }
#pragma unroll
        for (int d = 16; d; d >>= 1) s += __shfl_xor_sync(0xFFFFFFFFu, s, d);
        if (lane == 0) s_h1[o] = clip01(s + __ldg(&b1[k * 32 + o]));
    }
    __syncthreads();

    // ---- Layers 2+3 + psqt + output: warp 0 ----
    if (warp == 0) {
        const float* W2k = W2 + k * 32 * 32;
        float s = 0.0f;
#pragma unroll
        for (int i = 0; i < 32; i++)
            s += s_h1[i] * __ldg(&W2k[lane * 32 + i]);
        float h2 = clip01(s + __ldg(&b2[k * 32 + lane]));

        float p = h2 * __ldg(&W3[k * 32 + lane]);
#pragma unroll
        for (int d = 16; d; d >>= 1) p += __shfl_xor_sync(0xFFFFFFFFu, p, d);

        if (lane == 0) {
            float psqt = (psw - psb) * (0.5f - stm);
            out[row] = (p + __ldg(&b3[k]) + psqt) * SCALE_O;
        }
    }
}

// ---------------------------------------------------------------------------
// Harness entry
// ---------------------------------------------------------------------------
extern "C" void kernel_launch(void* const* d_in, const int* in_sizes, int n_in,
                              void* d_out, int out_size) {
    const float* wf    = (const float*)d_in[0];
    const float* bfeat = (const float*)d_in[1];
    const float* stm   = (const float*)d_in[2];
    const int*   bkt   = (const int*)  d_in[3];
    const float* W_ft  = (const float*)d_in[4];
    const float* b_ft  = (const float*)d_in[5];
    const float* W1    = (const float*)d_in[6];
    const float* b1    = (const float*)d_in[7];
    const float* W2    = (const float*)d_in[8];
    const float* b2    = (const float*)d_in[9];
    const float* W3    = (const float*)d_in[10];
    const float* b3    = (const float*)d_in[11];
    float* out = (float*)d_out;

    dim3 tg(NF / 32, (NOUT + 31) / 32);
    transpose_wft<<<tg, dim3(32, 8)>>>(W_ft);
    nnue_row<<<NROWS, 256>>>(wf, bfeat, stm, bkt, b_ft,
                             W1, b1, W2, b2, W3, b3, out);
}